// round 1
// baseline (speedup 1.0000x reference)
#include <cuda_runtime.h>
#include <math.h>

// Problem constants (fixed by the reference generator)
#define SEQ_LEN   65536
#define NN        256      // num nodes
#define NC        32       // num causes (roots)
#define LW        16       // nodes per layer
#define NL        14       // layers
#define NF        200      // X features
#define ROWS      128      // sequence rows per CTA
#define NTHREADS  256
#define VSTRIDE   129      // padded row stride for vals: bank = (node + row) % 32

#define SMEM_FLOATS (NN * VSTRIDE /*vals*/ + 240 * LW /*W stage*/)
#define SMEM_BYTES  (SMEM_FLOATS * 4 + NN * 4 /*acts*/ + NF * 4 /*x_idx*/)

__global__ __launch_bounds__(NTHREADS, 1)
void scm_kernel(const float* __restrict__ causes,
                const float* __restrict__ W,
                const float* __restrict__ eps,
                const int*   __restrict__ act_ids,
                const int*   __restrict__ x_idx,
                const int*   __restrict__ y_idx_p,
                float*       __restrict__ out)
{
    extern __shared__ float smem[];
    float* Vs   = smem;                        // [NN][VSTRIDE]
    float* Ws   = Vs + NN * VSTRIDE;           // [P][16], P <= 240
    int*   acts = (int*)(Ws + 240 * LW);       // [NN]
    int*   xs   = acts + NN;                   // [NF]

    const int tid  = threadIdx.x;
    const int row  = tid & (ROWS - 1);         // 0..127 (warp = 32 consecutive rows)
    const int half = tid >> 7;                 // 0/1: which 8 of the 16 layer outputs
    const int row0 = blockIdx.x * ROWS;
    const int rowg = row0 + row;

    if (tid < NN) acts[tid] = act_ids[tid];
    if (tid < NF) xs[tid]   = x_idx[tid];

    // Roots: vals[:, 0:32] = clip(causes, -5, 5)
    for (int idx = tid; idx < ROWS * NC; idx += NTHREADS) {
        int r = idx >> 5, c = idx & 31;
        float v = causes[(size_t)(row0 + r) * NC + c];
        v = fminf(fmaxf(v, -5.f), 5.f);
        Vs[c * VSTRIDE + r] = v;
    }
    __syncthreads();

    const int cbase = half * 8;

    for (int k = 0; k < NL; ++k) {
        const int P        = NC + k * LW;      // parents span nodes [0, P)
        const int nodebase = NC + k * LW;

        // Stage W[0:P, nodebase:nodebase+16] -> Ws[p*16 + c]
        for (int idx = tid; idx < P * LW; idx += NTHREADS) {
            int p = idx >> 4, c = idx & 15;
            Ws[idx] = W[p * NN + nodebase + c];
        }
        __syncthreads();

        // acc = eps slice for this row's 8 output nodes
        float acc[8];
        {
            const float4* e4 = (const float4*)(eps + (size_t)rowg * NN + nodebase + cbase);
            float4 e0 = e4[0], e1 = e4[1];
            acc[0] = e0.x; acc[1] = e0.y; acc[2] = e0.z; acc[3] = e0.w;
            acc[4] = e1.x; acc[5] = e1.y; acc[6] = e1.z; acc[7] = e1.w;
        }

        const float4* Ws4 = (const float4*)Ws;
        #pragma unroll 4
        for (int p = 0; p < P; ++p) {
            float  v  = Vs[p * VSTRIDE + row];           // conflict-free: bank=(p+row)%32
            float4 w0 = Ws4[p * 4 + half * 2 + 0];       // broadcast within warp
            float4 w1 = Ws4[p * 4 + half * 2 + 1];
            acc[0] = fmaf(v, w0.x, acc[0]);
            acc[1] = fmaf(v, w0.y, acc[1]);
            acc[2] = fmaf(v, w0.z, acc[2]);
            acc[3] = fmaf(v, w0.w, acc[3]);
            acc[4] = fmaf(v, w1.x, acc[4]);
            acc[5] = fmaf(v, w1.y, acc[5]);
            acc[6] = fmaf(v, w1.z, acc[6]);
            acc[7] = fmaf(v, w1.w, acc[7]);
        }

        // Activation + write back
        #pragma unroll
        for (int i = 0; i < 8; ++i) {
            int   node = nodebase + cbase + i;
            int   aid  = acts[node];
            float z = acc[i], a;
            if      (aid == 0) a = z;
            else if (aid == 1) a = tanhf(z);
            else if (aid == 2) a = fmaxf(z, 0.f);
            else               a = 1.f / (1.f + expf(-z));
            Vs[node * VSTRIDE + row] = a;
        }
        __syncthreads();
    }

    // Outputs: X = clip(nan_to_num(vals[:, x_idx]), -15, 15) then y = nan_to_num(vals[:, y_idx])
    const int yidx = y_idx_p ? *y_idx_p : (NN - 1);
    float* Xout = out;
    float* yout = out + (size_t)SEQ_LEN * NF;

    if (tid < ROWS) {
        float v = Vs[yidx * VSTRIDE + tid];
        if (v != v) v = 0.f;
        yout[row0 + tid] = v;
    }
    for (int idx = tid; idx < ROWS * NF; idx += NTHREADS) {
        int r = idx / NF, j = idx - r * NF;
        float v = Vs[xs[j] * VSTRIDE + r];
        if (v != v) v = 0.f;
        v = fminf(fmaxf(v, -15.f), 15.f);
        Xout[(size_t)(row0 + r) * NF + j] = v;
    }
}

extern "C" void kernel_launch(void* const* d_in, const int* in_sizes, int n_in,
                              void* d_out, int out_size)
{
    const float* causes  = (const float*)d_in[0];
    const float* W       = (const float*)d_in[1];
    const float* eps     = (const float*)d_in[2];
    const int*   act_ids = (const int*)d_in[3];
    const int*   x_idx   = (const int*)d_in[4];
    const int*   y_idx_p = (n_in > 5) ? (const int*)d_in[5] : nullptr;
    float*       out     = (float*)d_out;

    cudaFuncSetAttribute(scm_kernel, cudaFuncAttributeMaxDynamicSharedMemorySize, SMEM_BYTES);

    dim3 grid(SEQ_LEN / ROWS);   // 512 CTAs
    dim3 block(NTHREADS);
    scm_kernel<<<grid, block, SMEM_BYTES>>>(causes, W, eps, act_ids, x_idx, y_idx_p, out);
    (void)in_sizes; (void)out_size;
}

// round 2
// speedup vs baseline: 1.0938x; 1.0938x over previous
#include <cuda_runtime.h>
#include <math.h>

// Problem constants (fixed by the reference generator)
#define SEQ_LEN   65536
#define NN        256      // num nodes
#define NC        32       // num causes (roots)
#define LW        16       // nodes per layer
#define NL        14       // layers
#define NF        200      // X features
#define ROWS      128      // sequence rows per CTA
#define NTHREADS  512      // 16 warps: 128 rows x 4 col-groups
#define VSTRIDE   129      // padded row stride for vals: bank = (node + row) % 32

#define SMEM_FLOATS (NN * VSTRIDE /*vals*/ + 240 * LW /*W stage*/)
#define SMEM_BYTES  (SMEM_FLOATS * 4 + NN * 4 /*acts*/ + NF * 4 /*x_idx*/)

__global__ __launch_bounds__(NTHREADS, 1)
void scm_kernel(const float* __restrict__ causes,
                const float* __restrict__ W,
                const float* __restrict__ eps,
                const int*   __restrict__ act_ids,
                const int*   __restrict__ x_idx,
                const int*   __restrict__ y_idx_p,
                float*       __restrict__ out)
{
    extern __shared__ float smem[];
    float* Vs   = smem;                        // [NN][VSTRIDE]
    float* Ws   = Vs + NN * VSTRIDE;           // [P][16], P <= 240
    int*   acts = (int*)(Ws + 240 * LW);       // [NN]
    int*   xs   = acts + NN;                   // [NF]

    const int tid  = threadIdx.x;
    const int row  = tid & (ROWS - 1);         // 0..127 (warp = 32 consecutive rows)
    const int cg   = tid >> 7;                 // 0..3: which 4 of the 16 layer outputs
    const int row0 = blockIdx.x * ROWS;
    const int rowg = row0 + row;

    if (tid < NN) acts[tid] = act_ids[tid];
    if (tid < NF) xs[tid]   = x_idx[tid];

    // Roots: vals[:, 0:32] = clip(causes, -5, 5)
    for (int idx = tid; idx < ROWS * NC; idx += NTHREADS) {
        int r = idx >> 5, c = idx & 31;
        float v = causes[(size_t)(row0 + r) * NC + c];
        v = fminf(fmaxf(v, -5.f), 5.f);
        Vs[c * VSTRIDE + r] = v;
    }
    __syncthreads();

    const int cbase = cg * 4;

    for (int k = 0; k < NL; ++k) {
        const int P        = NC + k * LW;      // parents span nodes [0, P)
        const int nodebase = NC + k * LW;

        // Stage W[0:P, nodebase:nodebase+16] -> Ws[p*16 + c]
        for (int idx = tid; idx < P * LW; idx += NTHREADS) {
            int p = idx >> 4, c = idx & 15;
            Ws[idx] = W[p * NN + nodebase + c];
        }
        __syncthreads();

        // acc = eps slice for this row's 4 output nodes
        float acc[4];
        {
            float4 e0 = *(const float4*)(eps + (size_t)rowg * NN + nodebase + cbase);
            acc[0] = e0.x; acc[1] = e0.y; acc[2] = e0.z; acc[3] = e0.w;
        }

        const float4* Ws4 = (const float4*)Ws;
        #pragma unroll 8
        for (int p = 0; p < P; ++p) {
            float  v = Vs[p * VSTRIDE + row];            // conflict-free: bank=(p+row)%32
            float4 w = Ws4[p * 4 + cg];                  // broadcast within warp
            acc[0] = fmaf(v, w.x, acc[0]);
            acc[1] = fmaf(v, w.y, acc[1]);
            acc[2] = fmaf(v, w.z, acc[2]);
            acc[3] = fmaf(v, w.w, acc[3]);
        }

        // Activation + write back
        #pragma unroll
        for (int i = 0; i < 4; ++i) {
            int   node = nodebase + cbase + i;
            int   aid  = acts[node];
            float z = acc[i], a;
            if      (aid == 0) a = z;
            else if (aid == 1) a = tanhf(z);
            else if (aid == 2) a = fmaxf(z, 0.f);
            else               a = 1.f / (1.f + expf(-z));
            Vs[node * VSTRIDE + row] = a;
        }
        __syncthreads();
    }

    // Outputs: X = clip(nan_to_num(vals[:, x_idx]), -15, 15) then y = nan_to_num(vals[:, y_idx])
    const int yidx = y_idx_p ? *y_idx_p : (NN - 1);
    float* Xout = out;
    float* yout = out + (size_t)SEQ_LEN * NF;

    if (tid < ROWS) {
        float v = Vs[yidx * VSTRIDE + tid];
        if (v != v) v = 0.f;
        yout[row0 + tid] = v;
    }
    for (int idx = tid; idx < ROWS * NF; idx += NTHREADS) {
        int r = idx / NF, j = idx - r * NF;
        float v = Vs[xs[j] * VSTRIDE + r];
        if (v != v) v = 0.f;
        v = fminf(fmaxf(v, -15.f), 15.f);
        Xout[(size_t)(row0 + r) * NF + j] = v;
    }
}

extern "C" void kernel_launch(void* const* d_in, const int* in_sizes, int n_in,
                              void* d_out, int out_size)
{
    const float* causes  = (const float*)d_in[0];
    const float* W       = (const float*)d_in[1];
    const float* eps     = (const float*)d_in[2];
    const int*   act_ids = (const int*)d_in[3];
    const int*   x_idx   = (const int*)d_in[4];
    const int*   y_idx_p = (n_in > 5) ? (const int*)d_in[5] : nullptr;
    float*       out     = (float*)d_out;

    cudaFuncSetAttribute(scm_kernel, cudaFuncAttributeMaxDynamicSharedMemorySize, SMEM_BYTES);

    dim3 grid(SEQ_LEN / ROWS);   // 512 CTAs
    dim3 block(NTHREADS);
    scm_kernel<<<grid, block, SMEM_BYTES>>>(causes, W, eps, act_ids, x_idx, y_idx_p, out);
    (void)in_sizes; (void)out_size;
}